// round 9
// baseline (speedup 1.0000x reference)
#include <cuda_runtime.h>

typedef unsigned long long ull;

// Problem constants
#define BB    64    // batch
#define WDIM  128   // node feature dim (K of projection)
#define FDIM  64    // number of nodes
#define HH    4     // heads
#define DOUT  128   // out window per head

// Scratch (device globals; allocation-free)
__device__ float g_fs[BB * HH * FDIM * DOUT];   // [b][h][i][d]
__device__ float g_fd[BB * HH * FDIM * DOUT];   // [b][h][j][d]
__device__ float g_oh[BB * HH * FDIM * DOUT];   // [b][h][j][d] per-head outputs

// ---------------------------------------------------------------------------
// f32x2 packed-math helpers (Blackwell FFMA2 path — PTX only).
// ---------------------------------------------------------------------------
__device__ __forceinline__ ull fma2(ull a, ull b, ull c) {
    asm("fma.rn.f32x2 %0, %1, %2, %0;" : "+l"(c) : "l"(a), "l"(b));
    return c;
}
__device__ __forceinline__ ull add2(ull a, ull b) {
    ull d; asm("add.rn.f32x2 %0, %1, %2;" : "=l"(d) : "l"(a), "l"(b));
    return d;
}
__device__ __forceinline__ ull dup2(float x) {
    ull d; asm("mov.b64 %0, {%1, %1};" : "=l"(d) : "f"(x));
    return d;
}
__device__ __forceinline__ float2 u2f(ull v) {
    float2 f; asm("mov.b64 {%0, %1}, %2;" : "=f"(f.x), "=f"(f.y) : "l"(v));
    return f;
}
__device__ __forceinline__ ull abs2(ull v) {          // 2x LOP3 on alu pipe
    return v & 0x7fffffff7fffffffULL;
}

// ---------------------------------------------------------------------------
// Kernel 1: projections via FFMA2.  64x64 CTA tile, 64 KB smem -> 3 CTAs/SM.
// grid (64, 16): ct 0..7 -> fs col-block ct, 8..15 -> fd col-block ct-8.
// Column block = 64 global cols (half a head).  K=128 fully resident, one sync.
// Thread tile: 8 rows x 2 cols (row-pair packed accumulators):
//   per k: 8 FFMA2, 2 dups, 2 broadcast LDS.128 (A) + 1 LDS.64 (B).
// ---------------------------------------------------------------------------
__global__ __launch_bounds__(256, 3)
void proj_kernel(const float* __restrict__ x,
                 const float* __restrict__ Wsrc, const float* __restrict__ bsrc,
                 const float* __restrict__ Wdst, const float* __restrict__ bdst)
{
    extern __shared__ float sm[];
    float* As = sm;               // [128 k][64 r]  (32 KB)
    float* Bs = sm + 128 * 64;    // [128 k][64 c]  (32 KB)

    const int b  = blockIdx.x;
    const int ct = blockIdx.y;
    const int t  = threadIdx.x;

    const float* Wmat = (ct < 8) ? Wsrc : Wdst;
    const float* bias = (ct < 8) ? bsrc : bdst;
    const int cb = ct & 7;        // 64-col block within 512
    const int c0 = cb * 64;

    // Load A: x[b] is [128 w][64 f] contiguous -> As[w][f] directly
    {
        const float4* xb  = (const float4*)(x + (size_t)b * WDIM * FDIM);
        float4*       As4 = (float4*)As;
        #pragma unroll
        for (int idx = t; idx < 128 * 16; idx += 256) As4[idx] = xb[idx];
    }
    // Load B transposed: Bs[k][c] = Wmat[c0+c][k], c in 0..63
    #pragma unroll
    for (int idx = t; idx < 64 * 32; idx += 256) {
        int c  = idx & 63;
        int kq = idx >> 6;        // 0..31
        float4 v = *(const float4*)(Wmat + (size_t)(c0 + c) * WDIM + kq * 4);
        Bs[(kq * 4 + 0) * 64 + c] = v.x;
        Bs[(kq * 4 + 1) * 64 + c] = v.y;
        Bs[(kq * 4 + 2) * 64 + c] = v.z;
        Bs[(kq * 4 + 3) * 64 + c] = v.w;
    }
    __syncthreads();

    const int cx = t & 31;        // 32 col-threads * 2 cols = 64 cols
    const int ry = t >> 5;        // 8 row-groups * 8 rows = 64 rows
    const int r0 = ry * 8;
    const int cc = cx * 2;
    // lanes in a warp share ry -> A loads warp-broadcast; B LDS.64 conflict-free.

    ull acc2[4][2];               // [row-pair][col], lo = even row, hi = odd
    #pragma unroll
    for (int rp = 0; rp < 4; rp++) { acc2[rp][0] = 0ULL; acc2[rp][1] = 0ULL; }

    #pragma unroll 8
    for (int k = 0; k < 128; k++) {
        float4 a0 = *(const float4*)&As[k * 64 + r0];
        float4 a1 = *(const float4*)&As[k * 64 + r0 + 4];
        float2 bq = *(const float2*)&Bs[k * 64 + cc];
        ull bd0 = dup2(bq.x);
        ull bd1 = dup2(bq.y);
        const ull* p0 = (const ull*)&a0;
        const ull* p1 = (const ull*)&a1;
        ull av[4] = { p0[0], p0[1], p1[0], p1[1] };
        #pragma unroll
        for (int rp = 0; rp < 4; rp++) {
            acc2[rp][0] = fma2(av[rp], bd0, acc2[rp][0]);
            acc2[rp][1] = fma2(av[rp], bd1, acc2[rp][1]);
        }
    }

    // Epilogue: head = cb>>1 (64-block lies inside one head), d0 = (cb&1)*64 + cc
    const int head = cb >> 1;
    const int d0   = (cb & 1) * 64 + cc;
    float* outbase = ((ct < 8) ? g_fs : g_fd)
                   + (size_t)b * HH * FDIM * DOUT + (size_t)head * FDIM * DOUT;
    const float bv0 = bias[c0 + cc];
    const float bv1 = bias[c0 + cc + 1];

    #pragma unroll
    for (int rp = 0; rp < 4; rp++) {
        float2 q0 = u2f(acc2[rp][0]);   // col d0:   {row even, row odd}
        float2 q1 = u2f(acc2[rp][1]);   // col d0+1: {row even, row odd}
        float* rowA = outbase + (size_t)(r0 + 2 * rp) * DOUT + d0;
        float* rowB = rowA + DOUT;
        *(float2*)rowA = make_float2(q0.x + bv0, q1.x + bv1);
        *(float2*)rowB = make_float2(q0.y + bv0, q1.y + bv1);
    }
}

// ---------------------------------------------------------------------------
// Kernel 2: fused scores + softmax + aggregation, one CTA per (b,h).
//
// Exact rewrite: sum_d a_d * lrelu(fs_id + fd_jd, 0.2)
//              = 0.6*(As[i] + Ad[j]) + sum_d (0.4*a_d) * |fs_id + fd_jd|
// d packed into f32x2 pairs (halves summed at the end).
//
// smem trimmed to 66.5 KB (3 CTAs/SM): softmax probs ALIAS fdN's first 64
// columns — after the As/Ad sync, fdN row j is touched only by the warp that
// owns j (score reads, prob write, agg read), so no extra sync is needed.
// ---------------------------------------------------------------------------
#define NSTRIDE 130

__global__ __launch_bounds__(256, 3)
void attn_kernel(const float* __restrict__ attn)
{
    extern __shared__ float sm[];
    float* fsN   = sm;                     // [64 i][130]
    float* fdN   = fsN + FDIM * NSTRIDE;   // [64 j][130]; cols 0..63 reused as prob
    float* attn4 = fdN + FDIM * NSTRIDE;   // 128  (0.4 * attn[h])
    float* attnv = attn4 + 128;            // 128
    float* As_s  = attnv + 128;            // 64
    float* Ad_s  = As_s + 64;              // 64

    const int bh   = blockIdx.x;           // b*4 + h
    const int h    = bh & 3;
    const int t    = threadIdx.x;
    const int lane = t & 31;
    const int w    = t >> 5;

    const float* fs = g_fs + (size_t)bh * FDIM * DOUT;
    const float* fd = g_fd + (size_t)bh * FDIM * DOUT;

    // Stage fs/fd (row-major, padded stride), 8-byte chunks
    for (int p = t; p < FDIM * 64; p += 256) {     // 64 ull per row
        int i = p >> 6, dp = p & 63;
        *(ull*)&fsN[i * NSTRIDE + 2 * dp] = *(const ull*)&fs[i * DOUT + 2 * dp];
        *(ull*)&fdN[i * NSTRIDE + 2 * dp] = *(const ull*)&fd[i * DOUT + 2 * dp];
    }
    if (t < 128) {
        float a = attn[h * 128 + t];
        attnv[t] = a;
        attn4[t] = 0.4f * a;
    }
    __syncthreads();

    // As[i] = sum_d attn[d]*fs[i,d];  Ad[j] likewise
    if (t < 64) {
        float s = 0.f;
        #pragma unroll 4
        for (int d = 0; d < 128; d++) s = fmaf(attnv[d], fsN[t * NSTRIDE + d], s);
        As_s[t] = s;
    } else if (t < 128) {
        int j = t - 64;
        float s = 0.f;
        #pragma unroll 4
        for (int d = 0; d < 128; d++) s = fmaf(attnv[d], fdN[j * NSTRIDE + d], s);
        Ad_s[j] = s;
    }
    __syncthreads();
    // From here on, fdN row j is private to warp j>>3.

    // ---- Score phase: warp w owns j = w*8..w*8+7; lane owns i = lane, lane+32.
    const int jb = w * 8;
    const int i0 = lane, i1 = lane + 32;
    ull acc0[8], acc1[8];
    #pragma unroll
    for (int jj = 0; jj < 8; jj++) { acc0[jj] = 0ULL; acc1[jj] = 0ULL; }

    #pragma unroll 2
    for (int dp = 0; dp < 64; dp++) {
        ull a42 = *(const ull*)&attn4[2 * dp];               // broadcast
        ull f20 = *(const ull*)&fsN[i0 * NSTRIDE + 2 * dp];
        ull f21 = *(const ull*)&fsN[i1 * NSTRIDE + 2 * dp];
        #pragma unroll
        for (int jj = 0; jj < 8; jj++) {
            ull fd2 = *(const ull*)&fdN[(jb + jj) * NSTRIDE + 2 * dp];  // broadcast
            acc0[jj] = fma2(a42, abs2(add2(f20, fd2)), acc0[jj]);
            acc1[jj] = fma2(a42, abs2(add2(f21, fd2)), acc1[jj]);
        }
    }

    // ---- Softmax over i (64 sources) per j; probs overwrite fdN[j][0..63]
    const float As0 = As_s[i0], As1 = As_s[i1];
    #pragma unroll
    for (int jj = 0; jj < 8; jj++) {
        float Adv = Ad_s[jb + jj];
        float2 h0 = u2f(acc0[jj]);
        float2 h1 = u2f(acc1[jj]);
        float s0 = 0.6f * (As0 + Adv) + (h0.x + h0.y);
        float s1 = 0.6f * (As1 + Adv) + (h1.x + h1.y);
        float m = fmaxf(s0, s1);
        #pragma unroll
        for (int o = 16; o; o >>= 1) m = fmaxf(m, __shfl_xor_sync(0xffffffffu, m, o));
        float e0 = __expf(s0 - m);
        float e1 = __expf(s1 - m);
        float ssum = e0 + e1;
        #pragma unroll
        for (int o = 16; o; o >>= 1) ssum += __shfl_xor_sync(0xffffffffu, ssum, o);
        float inv = __frcp_rn(ssum);
        fdN[(jb + jj) * NSTRIDE + i0] = e0 * inv;
        fdN[(jb + jj) * NSTRIDE + i1] = e1 * inv;
    }
    __syncwarp();

    // ---- Aggregation: lane owns d-pairs at 2*lane and 2*(lane+32),
    // 8 j's register-blocked; prob read via broadcast LDS from fdN rows.
    ull o2[8][2];
    #pragma unroll
    for (int jj = 0; jj < 8; jj++) { o2[jj][0] = 0ULL; o2[jj][1] = 0ULL; }

    #pragma unroll 2
    for (int i = 0; i < 64; i++) {
        ull f20 = *(const ull*)&fsN[i * NSTRIDE + 2 * lane];
        ull f21 = *(const ull*)&fsN[i * NSTRIDE + 2 * (lane + 32)];
        #pragma unroll
        for (int jj = 0; jj < 8; jj++) {
            ull pd = dup2(fdN[(jb + jj) * NSTRIDE + i]);   // broadcast + dup
            o2[jj][0] = fma2(pd, f20, o2[jj][0]);
            o2[jj][1] = fma2(pd, f21, o2[jj][1]);
        }
    }

    float* oh = g_oh + (size_t)bh * FDIM * DOUT;
    #pragma unroll
    for (int jj = 0; jj < 8; jj++) {
        *(float2*)&oh[(jb + jj) * DOUT + 2 * lane]        = u2f(o2[jj][0]);
        *(float2*)&oh[(jb + jj) * DOUT + 2 * (lane + 32)] = u2f(o2[jj][1]);
    }
}

// ---------------------------------------------------------------------------
// Kernel 3: mean over heads + transpose.  out[b, d, j] = 0.25 * sum_h oh[b,h,j,d]
// ---------------------------------------------------------------------------
__global__ __launch_bounds__(256)
void reduce_kernel(float* __restrict__ out)
{
    __shared__ float s[64 * 129];
    const int b = blockIdx.x;
    const int t = threadIdx.x;
    const float* oh = g_oh + (size_t)b * HH * FDIM * DOUT;

    for (int idx = t; idx < FDIM * DOUT; idx += 256) {
        int j = idx >> 7, d = idx & 127;
        float v = oh[idx] + oh[idx + 8192] + oh[idx + 16384] + oh[idx + 24576];
        s[j * 129 + d] = 0.25f * v;
    }
    __syncthreads();

    float* ob = out + (size_t)b * DOUT * FDIM;
    for (int idx = t; idx < DOUT * FDIM; idx += 256) {
        int j = idx & 63, d = idx >> 6;
        ob[idx] = s[j * 129 + d];
    }
}

// ---------------------------------------------------------------------------
extern "C" void kernel_launch(void* const* d_in, const int* in_sizes, int n_in,
                              void* d_out, int out_size)
{
    const float* x    = (const float*)d_in[0];
    const float* Wsrc = (const float*)d_in[1];
    const float* bsrc = (const float*)d_in[2];
    const float* Wdst = (const float*)d_in[3];
    const float* bdst = (const float*)d_in[4];
    const float* attn = (const float*)d_in[5];
    float* out = (float*)d_out;

    const int smem1 = (128 * 64 + 128 * 64) * 4;                        // 64 KB
    const int smem2 = (2 * FDIM * NSTRIDE + 128 + 128 + 64 + 64) * 4;   // 68096 B

    cudaFuncSetAttribute(proj_kernel, cudaFuncAttributeMaxDynamicSharedMemorySize, smem1);
    cudaFuncSetAttribute(attn_kernel, cudaFuncAttributeMaxDynamicSharedMemorySize, smem2);

    proj_kernel<<<dim3(BB, 16), 256, smem1>>>(x, Wsrc, bsrc, Wdst, bdst);
    attn_kernel<<<BB * HH, 256, smem2>>>(attn);
    reduce_kernel<<<BB, 256>>>(out);
}

// round 11
// speedup vs baseline: 1.2913x; 1.2913x over previous
#include <cuda_runtime.h>
#include <cuda_bf16.h>
#include <cstdint>

typedef unsigned long long ull;

// Problem constants
#define BB    64    // batch
#define WDIM  128   // node feature dim (K of projection)
#define FDIM  64    // number of nodes
#define HH    4     // heads
#define DOUT  128   // out window per head

// Scratch (device globals; allocation-free)
__device__ float g_fs[BB * HH * FDIM * DOUT];   // [b][h][i][d]
__device__ float g_fd[BB * HH * FDIM * DOUT];   // [b][h][j][d]
__device__ float g_oh[BB * HH * FDIM * DOUT];   // [b][h][j][d] per-head outputs

// Fragment-ordered bf16 hi/lo operands for mma.sync m16n8k16.
// One uint4 (16B) per (row, s, u):  {pair(k0,k0+1) hi, pair(k0+8,k0+9) hi,
//                                    pair(k0,k0+1) lo, pair(k0+8,k0+9) lo}
// with k0 = 16*s + 2*u.  Index = row*32 + s*4 + u.
__device__ uint4 g_a[4096 * 32];   // A = X^T rows [b*64+f], k = w
__device__ uint4 g_w[1024 * 32];   // rows 0..511 = Wsrc, 512..1023 = Wdst

// ---------------------------------------------------------------------------
// f32x2 packed-math helpers (attn kernel)
// ---------------------------------------------------------------------------
__device__ __forceinline__ ull fma2(ull a, ull b, ull c) {
    asm("fma.rn.f32x2 %0, %1, %2, %0;" : "+l"(c) : "l"(a), "l"(b));
    return c;
}
__device__ __forceinline__ ull add2(ull a, ull b) {
    ull d; asm("add.rn.f32x2 %0, %1, %2;" : "=l"(d) : "l"(a), "l"(b));
    return d;
}
__device__ __forceinline__ ull dup2(float x) {
    ull d; asm("mov.b64 %0, {%1, %1};" : "=l"(d) : "f"(x));
    return d;
}
__device__ __forceinline__ float2 u2f(ull v) {
    float2 f; asm("mov.b64 {%0, %1}, %2;" : "=f"(f.x), "=f"(f.y) : "l"(v));
    return f;
}
__device__ __forceinline__ ull abs2(ull v) { return v & 0x7fffffff7fffffffULL; }

// ---------------------------------------------------------------------------
// bf16 pack helper: 4 floats -> {hi pair01, hi pair23, lo pair01, lo pair23}
// ---------------------------------------------------------------------------
__device__ __forceinline__ uint4 pack_hilo(float v0, float v1, float v2, float v3) {
    __nv_bfloat16 h0 = __float2bfloat16(v0), h1 = __float2bfloat16(v1);
    __nv_bfloat16 h2 = __float2bfloat16(v2), h3 = __float2bfloat16(v3);
    __nv_bfloat16 l0 = __float2bfloat16(v0 - __bfloat162float(h0));
    __nv_bfloat16 l1 = __float2bfloat16(v1 - __bfloat162float(h1));
    __nv_bfloat16 l2 = __float2bfloat16(v2 - __bfloat162float(h2));
    __nv_bfloat16 l3 = __float2bfloat16(v3 - __bfloat162float(h3));
    uint4 r;
    r.x = (uint32_t)__bfloat16_as_ushort(h0) | ((uint32_t)__bfloat16_as_ushort(h1) << 16);
    r.y = (uint32_t)__bfloat16_as_ushort(h2) | ((uint32_t)__bfloat16_as_ushort(h3) << 16);
    r.z = (uint32_t)__bfloat16_as_ushort(l0) | ((uint32_t)__bfloat16_as_ushort(l1) << 16);
    r.w = (uint32_t)__bfloat16_as_ushort(l2) | ((uint32_t)__bfloat16_as_ushort(l3) << 16);
    return r;
}

// mma.sync m16n8k16 row.col f32.bf16.bf16.f32, accumulate in place
__device__ __forceinline__ void mma_bf16(float* d, uint32_t a0, uint32_t a1,
                                         uint32_t a2, uint32_t a3,
                                         uint32_t b0, uint32_t b1) {
    asm volatile(
        "mma.sync.aligned.m16n8k16.row.col.f32.bf16.bf16.f32 "
        "{%0,%1,%2,%3}, {%4,%5,%6,%7}, {%8,%9}, {%0,%1,%2,%3};"
        : "+f"(d[0]), "+f"(d[1]), "+f"(d[2]), "+f"(d[3])
        : "r"(a0), "r"(a1), "r"(a2), "r"(a3), "r"(b0), "r"(b1));
}

// ---------------------------------------------------------------------------
// conv_w: W fp32 -> fragment-ordered bf16 hi/lo.  32768 blocks of 16B.
// Row n < 512 -> Wsrc, else Wdst.  Per warp: lanes cover one full 512B row.
// ---------------------------------------------------------------------------
__global__ __launch_bounds__(256)
void conv_w(const float* __restrict__ Wsrc, const float* __restrict__ Wdst)
{
    int q  = blockIdx.x * 256 + threadIdx.x;   // 0..32767
    int n  = q >> 5, r5 = q & 31;
    int s  = r5 >> 2, u = r5 & 3;
    int k0 = 16 * s + 2 * u;
    const float* row = (n < 512) ? Wsrc + (size_t)n * 128
                                 : Wdst + (size_t)(n - 512) * 128;
    float2 pa = *(const float2*)(row + k0);
    float2 pb = *(const float2*)(row + k0 + 8);
    g_w[q] = pack_hilo(pa.x, pa.y, pb.x, pb.y);
}

// ---------------------------------------------------------------------------
// conv_x: x[b][w][f] fp32 -> A rows [b*64+f][k=w], fragment-ordered hi/lo.
// smem transpose, then per-thread gather of the 4 fragment values.
// ---------------------------------------------------------------------------
__global__ __launch_bounds__(256)
void conv_x(const float* __restrict__ x)
{
    __shared__ float sm[128 * 65];
    const int b = blockIdx.x, t = threadIdx.x;
    const float* xb = x + (size_t)b * 8192;
    for (int idx = t; idx < 8192; idx += 256) {
        int w = idx >> 6, f = idx & 63;
        sm[w * 65 + f] = xb[idx];
    }
    __syncthreads();
    #pragma unroll
    for (int it = 0; it < 8; it++) {
        int q  = it * 256 + t;        // 0..2047
        int f  = q >> 5, r5 = q & 31;
        int s  = r5 >> 2, u = r5 & 3;
        int k0 = 16 * s + 2 * u;
        float v0 = sm[(k0)     * 65 + f];
        float v1 = sm[(k0 + 1) * 65 + f];
        float v2 = sm[(k0 + 8) * 65 + f];
        float v3 = sm[(k0 + 9) * 65 + f];
        g_a[(size_t)(b * 64 + f) * 32 + r5] = pack_hilo(v0, v1, v2, v3);
    }
}

// ---------------------------------------------------------------------------
// proj_mma: C[4096,1024] = A @ Wcat^T via bf16 HMMA with hi/lo compensation.
// grid (64, 8), 256 threads = 8 warps (2 m-warps x 4 n-warps).
// CTA tile 64x128, warp tile 32x32 (2 m-frags x 4 n-frags), K=128 (8 k-steps).
// D += Ah*Bh + Ah*Bl + Al*Bh  (fp32 accumulators; Al*Bl dropped ~2^-18).
// Fragments loaded directly from the fragment-ordered global arrays
// (L1/L2-resident: W reused by all 64 row tiles, A by all 8 col tiles).
// ---------------------------------------------------------------------------
__global__ __launch_bounds__(256)
void proj_mma(const float* __restrict__ bsrc, const float* __restrict__ bdst)
{
    const int t    = threadIdx.x;
    const int w    = t >> 5;
    const int lane = t & 31;
    const int g    = lane >> 2;     // fragment group row / col
    const int tt   = lane & 3;      // fragment quad

    const int rowBase = blockIdx.x * 64  + (w >> 2) * 32;
    const int colBase = blockIdx.y * 128 + (w & 3) * 32;

    float acc[2][4][4];
    #pragma unroll
    for (int mf = 0; mf < 2; mf++)
        #pragma unroll
        for (int nf = 0; nf < 4; nf++)
            #pragma unroll
            for (int e = 0; e < 4; e++) acc[mf][nf][e] = 0.f;

    #pragma unroll
    for (int s = 0; s < 8; s++) {
        uint4 a[2][2];
        #pragma unroll
        for (int mf = 0; mf < 2; mf++) {
            int r0 = rowBase + mf * 16 + g;
            a[mf][0] = g_a[(size_t)r0 * 32 + s * 4 + tt];        // a0h,a2h,a0l,a2l
            a[mf][1] = g_a[(size_t)(r0 + 8) * 32 + s * 4 + tt];  // a1h,a3h,a1l,a3l
        }
        uint4 bf[4];
        #pragma unroll
        for (int nf = 0; nf < 4; nf++) {
            int n0 = colBase + nf * 8 + g;
            bf[nf] = g_w[(size_t)n0 * 32 + s * 4 + tt];          // b0h,b1h,b0l,b1l
        }
        #pragma unroll
        for (int mf = 0; mf < 2; mf++)
            #pragma unroll
            for (int nf = 0; nf < 4; nf++) {
                // Ah * Bh
                mma_bf16(acc[mf][nf], a[mf][0].x, a[mf][1].x, a[mf][0].y, a[mf][1].y,
                         bf[nf].x, bf[nf].y);
                // Ah * Bl
                mma_bf16(acc[mf][nf], a[mf][0].x, a[mf][1].x, a[mf][0].y, a[mf][1].y,
                         bf[nf].z, bf[nf].w);
                // Al * Bh
                mma_bf16(acc[mf][nf], a[mf][0].z, a[mf][1].z, a[mf][0].w, a[mf][1].w,
                         bf[nf].x, bf[nf].y);
            }
    }

    // Epilogue: D frag (g, 2tt),(g+8, 2tt); add bias; route fs/fd by column.
    const bool is_fs = (colBase < 512);
    const float* bias = is_fs ? bsrc : bdst;
    #pragma unroll
    for (int nf = 0; nf < 4; nf++) {
        int cg   = colBase + nf * 8 + 2 * tt;      // global col, even
        int head = (cg >> 7) & 3;
        int d    = cg & 127;
        int bidx = cg & 511;
        float2 bv = *(const float2*)(bias + bidx);
        float* arr = is_fs ? g_fs : g_fd;
        #pragma unroll
        for (int mf = 0; mf < 2; mf++) {
            int r = rowBase + mf * 16 + g;
            int bb = r >> 6, ff = r & 63;
            float* base = arr + ((size_t)(bb * 4 + head) * 64 + ff) * 128 + d;
            *(float2*)base = make_float2(acc[mf][nf][0] + bv.x, acc[mf][nf][1] + bv.y);
            float* base8 = base + 8 * 128;         // row r+8 (same bb, ff+8)
            *(float2*)base8 = make_float2(acc[mf][nf][2] + bv.x, acc[mf][nf][3] + bv.y);
        }
    }
}

// ---------------------------------------------------------------------------
// Kernel 2: fused scores + softmax + aggregation, one CTA per (b,h).  (R5)
// score rewrite: sum_d a_d*lrelu(fs+fd) = 0.6*(As[i]+Ad[j]) + sum_d (0.4 a_d)|fs+fd|
// ---------------------------------------------------------------------------
#define NSTRIDE 130

__global__ __launch_bounds__(256, 2)
void attn_kernel(const float* __restrict__ attn)
{
    extern __shared__ float sm[];
    float* fsN   = sm;                     // [64 i][130]
    float* fdN   = fsN + FDIM * NSTRIDE;   // [64 j][130]
    float* attn4 = fdN + FDIM * NSTRIDE;   // 128  (0.4 * attn[h])
    float* attnv = attn4 + 128;            // 128
    float* As_s  = attnv + 128;            // 64
    float* Ad_s  = As_s + 64;              // 64
    float* prob  = Ad_s + 64;              // [64 j][64 i]

    const int bh   = blockIdx.x;
    const int h    = bh & 3;
    const int t    = threadIdx.x;
    const int lane = t & 31;
    const int w    = t >> 5;

    const float* fs = g_fs + (size_t)bh * FDIM * DOUT;
    const float* fd = g_fd + (size_t)bh * FDIM * DOUT;

    for (int p = t; p < FDIM * 64; p += 256) {
        int i = p >> 6, dp = p & 63;
        *(ull*)&fsN[i * NSTRIDE + 2 * dp] = *(const ull*)&fs[i * DOUT + 2 * dp];
        *(ull*)&fdN[i * NSTRIDE + 2 * dp] = *(const ull*)&fd[i * DOUT + 2 * dp];
    }
    if (t < 128) {
        float a = attn[h * 128 + t];
        attnv[t] = a;
        attn4[t] = 0.4f * a;
    }
    __syncthreads();

    if (t < 64) {
        float s = 0.f;
        #pragma unroll 4
        for (int d = 0; d < 128; d++) s = fmaf(attnv[d], fsN[t * NSTRIDE + d], s);
        As_s[t] = s;
    } else if (t < 128) {
        int j = t - 64;
        float s = 0.f;
        #pragma unroll 4
        for (int d = 0; d < 128; d++) s = fmaf(attnv[d], fdN[j * NSTRIDE + d], s);
        Ad_s[j] = s;
    }
    __syncthreads();

    const int jb = w * 8;
    const int i0 = lane, i1 = lane + 32;
    ull acc0[8], acc1[8];
    #pragma unroll
    for (int jj = 0; jj < 8; jj++) { acc0[jj] = 0ULL; acc1[jj] = 0ULL; }

    #pragma unroll 2
    for (int dp = 0; dp < 64; dp++) {
        ull a42 = *(const ull*)&attn4[2 * dp];
        ull f20 = *(const ull*)&fsN[i0 * NSTRIDE + 2 * dp];
        ull f21 = *(const ull*)&fsN[i1 * NSTRIDE + 2 * dp];
        #pragma unroll
        for (int jj = 0; jj < 8; jj++) {
            ull fd2 = *(const ull*)&fdN[(jb + jj) * NSTRIDE + 2 * dp];
            acc0[jj] = fma2(a42, abs2(add2(f20, fd2)), acc0[jj]);
            acc1[jj] = fma2(a42, abs2(add2(f21, fd2)), acc1[jj]);
        }
    }

    const float As0 = As_s[i0], As1 = As_s[i1];
    #pragma unroll
    for (int jj = 0; jj < 8; jj++) {
        float Adv = Ad_s[jb + jj];
        float2 h0 = u2f(acc0[jj]);
        float2 h1 = u2f(acc1[jj]);
        float s0 = 0.6f * (As0 + Adv) + (h0.x + h0.y);
        float s1 = 0.6f * (As1 + Adv) + (h1.x + h1.y);
        float m = fmaxf(s0, s1);
        #pragma unroll
        for (int o = 16; o; o >>= 1) m = fmaxf(m, __shfl_xor_sync(0xffffffffu, m, o));
        float e0 = __expf(s0 - m);
        float e1 = __expf(s1 - m);
        float ssum = e0 + e1;
        #pragma unroll
        for (int o = 16; o; o >>= 1) ssum += __shfl_xor_sync(0xffffffffu, ssum, o);
        float inv = __frcp_rn(ssum);
        prob[(jb + jj) * 64 + i0] = e0 * inv;
        prob[(jb + jj) * 64 + i1] = e1 * inv;
    }
    __syncwarp();

    ull o2[8][2];
    #pragma unroll
    for (int jj = 0; jj < 8; jj++) { o2[jj][0] = 0ULL; o2[jj][1] = 0ULL; }

    #pragma unroll 2
    for (int i = 0; i < 64; i++) {
        ull f20 = *(const ull*)&fsN[i * NSTRIDE + 2 * lane];
        ull f21 = *(const ull*)&fsN[i * NSTRIDE + 2 * (lane + 32)];
        #pragma unroll
        for (int jj = 0; jj < 8; jj++) {
            ull pd = dup2(prob[(jb + jj) * 64 + i]);
            o2[jj][0] = fma2(pd, f20, o2[jj][0]);
            o2[jj][1] = fma2(pd, f21, o2[jj][1]);
        }
    }

    float* oh = g_oh + (size_t)bh * FDIM * DOUT;
    #pragma unroll
    for (int jj = 0; jj < 8; jj++) {
        *(float2*)&oh[(jb + jj) * DOUT + 2 * lane]        = u2f(o2[jj][0]);
        *(float2*)&oh[(jb + jj) * DOUT + 2 * (lane + 32)] = u2f(o2[jj][1]);
    }
}

// ---------------------------------------------------------------------------
// Kernel 3: mean over heads + transpose.
// ---------------------------------------------------------------------------
__global__ __launch_bounds__(256)
void reduce_kernel(float* __restrict__ out)
{
    __shared__ float s[64 * 129];
    const int b = blockIdx.x;
    const int t = threadIdx.x;
    const float* oh = g_oh + (size_t)b * HH * FDIM * DOUT;

    for (int idx = t; idx < FDIM * DOUT; idx += 256) {
        int j = idx >> 7, d = idx & 127;
        float v = oh[idx] + oh[idx + 8192] + oh[idx + 16384] + oh[idx + 24576];
        s[j * 129 + d] = 0.25f * v;
    }
    __syncthreads();

    float* ob = out + (size_t)b * DOUT * FDIM;
    for (int idx = t; idx < DOUT * FDIM; idx += 256) {
        int j = idx & 63, d = idx >> 6;
        ob[idx] = s[j * 129 + d];
    }
}

// ---------------------------------------------------------------------------
extern "C" void kernel_launch(void* const* d_in, const int* in_sizes, int n_in,
                              void* d_out, int out_size)
{
    const float* x    = (const float*)d_in[0];
    const float* Wsrc = (const float*)d_in[1];
    const float* bsrc = (const float*)d_in[2];
    const float* Wdst = (const float*)d_in[3];
    const float* bdst = (const float*)d_in[4];
    const float* attn = (const float*)d_in[5];
    float* out = (float*)d_out;

    const int smem2 = (2 * FDIM * NSTRIDE + 128 + 128 + 64 + 64 + 4096) * 4;  // 84480 B

    cudaFuncSetAttribute(attn_kernel, cudaFuncAttributeMaxDynamicSharedMemorySize, smem2);

    conv_w<<<128, 256>>>(Wsrc, Wdst);
    conv_x<<<64, 256>>>(x);
    proj_mma<<<dim3(64, 8), 256>>>(bsrc, bdst);
    attn_kernel<<<BB * HH, 256, smem2>>>(attn);
    reduce_kernel<<<BB, 256>>>(out);
}